// round 15
// baseline (speedup 1.0000x reference)
#include <cuda_runtime.h>
#include <cuda_fp16.h>
#include <cstdint>

#define BB 8
#define TT 512
#define SS 512
#define HH 128

// scratch (allocation-free rule: __device__ globals)
__device__ uint32_t g_WS2[BB*TT/2*HH];   // half2: (WS[t_even], WS[t_odd]) per h
__device__ uint32_t g_WH2[BB*SS*HH];     // half2: (WH, WH) duplicated
__device__ uint32_t g_V2 [HH];           // half2: (v, v) duplicated
__device__ float    g_SC [BB*TT*SS];     // raw masked scores (8 MB, L2-resident)

__device__ __forceinline__ uint32_t tanh2_u(uint32_t a){
    uint32_t r; asm("tanh.approx.f16x2 %0, %1;" : "=r"(r) : "r"(a)); return r;
}
__device__ __forceinline__ void cp16(uint32_t smem_dst, const void* gsrc){
    asm volatile("cp.async.ca.shared.global [%0], [%1], 16;" :: "r"(smem_dst), "l"(gsrc));
}
#define CP_COMMIT() asm volatile("cp.async.commit_group;")
template<int N> __device__ __forceinline__ void cp_wait(){
    asm volatile("cp.async.wait_group %0;" :: "n"(N));
}

// ---------------------------------------------------------------------------
// K1: projections. grid (128, 2): y=0 -> WS(query,W_s) -> g_WS2 (t-paired h2),
//                                 y=1 -> WH(enc,W_h)   -> g_WH2 (dup h2).
// Block (0,0) also packs v into g_V2.
// ---------------------------------------------------------------------------
__global__ __launch_bounds__(256) void k_proj(
    const float* __restrict__ q, const float* __restrict__ enc,
    const float* __restrict__ Ws, const float* __restrict__ Wh,
    const float* __restrict__ vvec)
{
    extern __shared__ float sm[];
    float* insm = sm;            // 32 x 128
    float* Wsm  = sm + 32*128;   // 128 cols x 36

    const float* in; const float* W;
    if (blockIdx.y == 0) { in = q;   W = Ws; }
    else                 { in = enc; W = Wh; }
    int tid = threadIdx.x;
    int i0 = blockIdx.x * 32;

    if (blockIdx.x == 0 && blockIdx.y == 0 && tid < 128) {
        __half2 d = __half2half2(__float2half_rn(vvec[tid]));
        g_V2[tid] = *(uint32_t*)&d;
    }

    {
        const float4* inv = (const float4*)(in + i0*128);
        float4* insv = (float4*)insm;
        #pragma unroll
        for (int k = 0; k < 4; k++) insv[tid + 256*k] = inv[tid + 256*k];
    }

    int cg = tid & 31;
    int rg = tid >> 5;
    float acc[4][4];
    #pragma unroll
    for (int r = 0; r < 4; r++)
        #pragma unroll
        for (int j = 0; j < 4; j++) acc[r][j] = 0.f;

    #pragma unroll 1
    for (int hc = 0; hc < 4; hc++) {
        __syncthreads();
        #pragma unroll
        for (int k = 0; k < 4; k++) {
            int idx = tid + 256*k;
            int col = idx >> 3, kk = idx & 7;
            float4 w = *(const float4*)(W + col*128 + hc*32 + kk*4);
            *(float4*)(Wsm + col*36 + kk*4) = w;
        }
        __syncthreads();
        #pragma unroll
        for (int k8 = 0; k8 < 8; k8++) {
            float4 cv[4];
            #pragma unroll
            for (int j = 0; j < 4; j++)
                cv[j] = *(const float4*)(Wsm + (cg + 32*j)*36 + k8*4);
            float4 rv[4];
            #pragma unroll
            for (int r = 0; r < 4; r++)
                rv[r] = *(const float4*)(insm + (rg*4 + r)*128 + hc*32 + k8*4);
            #pragma unroll
            for (int r = 0; r < 4; r++)
                #pragma unroll
                for (int j = 0; j < 4; j++) {
                    acc[r][j] += rv[r].x*cv[j].x;
                    acc[r][j] += rv[r].y*cv[j].y;
                    acc[r][j] += rv[r].z*cv[j].z;
                    acc[r][j] += rv[r].w*cv[j].w;
                }
        }
    }
    if (blockIdx.y == 0) {
        #pragma unroll
        for (int r = 0; r < 4; r += 2)
            #pragma unroll
            for (int j = 0; j < 4; j++) {
                __half2 p = __floats2half2_rn(acc[r][j], acc[r+1][j]);  // x=even t
                int pair = (i0 + rg*4 + r) >> 1;
                g_WS2[pair*128 + cg + 32*j] = *(uint32_t*)&p;
            }
    } else {
        #pragma unroll
        for (int r = 0; r < 4; r++)
            #pragma unroll
            for (int j = 0; j < 4; j++) {
                __half2 d = __half2half2(__float2half_rn(acc[r][j]));
                g_WH2[(i0 + rg*4 + r)*128 + cg + 32*j] = *(uint32_t*)&d;
            }
    }
}

// ---------------------------------------------------------------------------
// K2: scores only. grid 2048 = (b, t-tile of 16, s-chunk of 64).
// Early-exit (write zeros) when whole s-chunk masked.
// ---------------------------------------------------------------------------
__global__ __launch_bounds__(256) void k_scores(
    const int* __restrict__ lens)
{
    __shared__ uint32_t s_wh[64*132];   // transposed s-chunk, pad 132
    __shared__ uint32_t s_ws[8*128];    // 8 t-pairs x 128 h
    __shared__ uint32_t s_v [128];      // dup half2 of v

    int bx = blockIdx.x;
    int b  = bx >> 8;
    int tt = (bx >> 3) & 31;
    int sc = bx & 7;
    int t0 = tt*16, s0 = sc*64;
    int tid = threadIdx.x;
    int len = __ldg(&lens[b]);

    if (s0 >= len) {   // fully masked: write zeros (reference quirk)
        int r = tid >> 4, c4 = tid & 15;
        *(float4*)(g_SC + (b*TT + t0 + r)*SS + s0 + c4*4) = make_float4(0.f,0.f,0.f,0.f);
        return;
    }

    uint32_t smbase = (uint32_t)__cvta_generic_to_shared(s_wh);
    {   // stage WH chunk (transposed, cp.async)
        const uint32_t* src = g_WH2 + (b*SS + s0)*128;
        #pragma unroll
        for (int k = 0; k < 8; k++) {
            int idx = tid + 256*k;            // 2048 x 16B
            int ss = idx >> 5, kk = idx & 31;
            cp16(smbase + (ss*132 + kk*4)*4, src + ss*128 + kk*4);
        }
        CP_COMMIT();
    }
    {   // stage ws pairs + v
        const uint32_t* wsrc = g_WS2 + (b*(TT/2) + t0/2)*128;
        #pragma unroll
        for (int k = 0; k < 4; k++) s_ws[tid + 256*k] = wsrc[tid + 256*k];
        if (tid < 128) s_v[tid] = g_V2[tid];
    }
    cp_wait<0>();
    __syncthreads();

    int warp = tid >> 5, lane = tid & 31;
    int tq = warp >> 1, sh = warp & 1;
    int s  = sh*32 + lane;
    const uint32_t* wsA = s_ws + (tq*2 + 0)*128;   // (t=4tq+0, 4tq+1)
    const uint32_t* wsB = s_ws + (tq*2 + 1)*128;   // (t=4tq+2, 4tq+3)
    const uint32_t* whrow = s_wh + s*132;

    float a0 = 0.f, a1 = 0.f, a2 = 0.f, a3 = 0.f;
    #pragma unroll
    for (int hb = 0; hb < 128; hb += 8) {      // flush f16 accumulators every 8 h
        __half2 accA = __float2half2_rn(0.f);
        __half2 accB = __float2half2_rn(0.f);
        #pragma unroll
        for (int g = 0; g < 8; g += 4) {
            uint4 wh4 = *(const uint4*)(whrow + hb + g);
            uint4 wA4 = *(const uint4*)(wsA + hb + g);
            uint4 wB4 = *(const uint4*)(wsB + hb + g);
            uint4 vv4 = *(const uint4*)(s_v + hb + g);
            #define STEP(WH, WA, WB, VV)                                     \
            {                                                                \
                __half2 hw = *(__half2*)&(WH);                               \
                __half2 aA = __hadd2(hw, *(__half2*)&(WA));                  \
                __half2 aB = __hadd2(hw, *(__half2*)&(WB));                  \
                uint32_t tA = tanh2_u(*(uint32_t*)&aA);                      \
                uint32_t tB = tanh2_u(*(uint32_t*)&aB);                      \
                __half2 v2 = *(__half2*)&(VV);                               \
                accA = __hfma2(v2, *(__half2*)&tA, accA);                    \
                accB = __hfma2(v2, *(__half2*)&tB, accB);                    \
            }
            STEP(wh4.x, wA4.x, wB4.x, vv4.x)
            STEP(wh4.y, wA4.y, wB4.y, vv4.y)
            STEP(wh4.z, wA4.z, wB4.z, vv4.z)
            STEP(wh4.w, wA4.w, wB4.w, vv4.w)
            #undef STEP
        }
        float2 fA = __half22float2(accA);
        float2 fB = __half22float2(accB);
        a0 += fA.x; a1 += fA.y;
        a2 += fB.x; a3 += fB.y;
    }
    int sg = s0 + s;
    float m = (sg < len) ? 1.f : 0.f;          // reference quirk: zero, not -inf
    g_SC[(b*TT + t0 + tq*4 + 0)*SS + sg] = a0 * m;
    g_SC[(b*TT + t0 + tq*4 + 1)*SS + sg] = a1 * m;
    g_SC[(b*TT + t0 + tq*4 + 2)*SS + sg] = a2 * m;
    g_SC[(b*TT + t0 + tq*4 + 3)*SS + sg] = a3 * m;
}

// ---------------------------------------------------------------------------
// K3: softmax + ct + OUTPUT GEMM (fused k_out). grid 512 = (b, t-tile of 8),
// 256 threads, 4 CTAs/SM. After ct reduce, concat=[ct,q] is built in smem and
// out = tanh(W_out . concat + b) is computed in-place (no g_CT round trip).
// ---------------------------------------------------------------------------
__global__ __launch_bounds__(256, 4) void k_smct(
    const float* __restrict__ enc, const float* __restrict__ q,
    const float* __restrict__ Wout, const float* __restrict__ bias,
    float* __restrict__ out)
{
    __shared__ float buf[8*8*128];   // 32KB; scores -> partials -> concat+W
    __shared__ float invsum[8];
    float* scores = buf;

    int tid = threadIdx.x;
    int b  = blockIdx.x >> 6;
    int t0 = (blockIdx.x & 63) * 8;
    int warp = tid >> 5, lane = tid & 31;

    {   // stage scores (cp.async, 16 KB, coalesced)
        uint32_t smbase = (uint32_t)__cvta_generic_to_shared(buf);
        const float* src = g_SC + (b*TT + t0)*SS;
        #pragma unroll
        for (int k = 0; k < 4; k++) {
            int idx = tid + 256*k;            // 1024 x 16B
            cp16(smbase + idx*16, src + idx*4);
        }
        CP_COMMIT();
        cp_wait<0>();
        __syncthreads();
    }

    // ---- softmax over full 512 (zeros included); 1 warp per row ----
    {
        int t = warp;
        float* row = scores + t*512;
        float loc[16];
        float mx = -1e30f;
        #pragma unroll
        for (int k = 0; k < 16; k++) { loc[k] = row[lane + 32*k]; mx = fmaxf(mx, loc[k]); }
        #pragma unroll
        for (int o = 16; o > 0; o >>= 1) mx = fmaxf(mx, __shfl_xor_sync(0xffffffffu, mx, o));
        float sum = 0.f;
        #pragma unroll
        for (int k = 0; k < 16; k++) {
            float p = __expf(loc[k] - mx);
            row[lane + 32*k] = p;
            sum += p;
        }
        #pragma unroll
        for (int o = 16; o > 0; o >>= 1) sum += __shfl_xor_sync(0xffffffffu, sum, o);
        if (lane == 0) invsum[t] = 1.f / sum;
    }
    __syncthreads();

    // ---- ct partials: warp w covers s in [w*64, w*64+64), all 8 t ----
    int h0 = lane * 4;
    int sbase = warp * 64;
    float4 acc[8];
    #pragma unroll
    for (int t = 0; t < 8; t++) acc[t] = make_float4(0.f,0.f,0.f,0.f);

    const float* eb = enc + (b*SS)*128;
    #pragma unroll 2
    for (int s4 = 0; s4 < 16; s4++) {
        float4 e0 = __ldg((const float4*)(eb + (sbase + s4*4 + 0)*128 + h0));
        float4 e1 = __ldg((const float4*)(eb + (sbase + s4*4 + 1)*128 + h0));
        float4 e2 = __ldg((const float4*)(eb + (sbase + s4*4 + 2)*128 + h0));
        float4 e3 = __ldg((const float4*)(eb + (sbase + s4*4 + 3)*128 + h0));
        const float* ps = scores + sbase + s4*4;
        #pragma unroll
        for (int t = 0; t < 8; t++) {
            float4 p = *(const float4*)(ps + t*512);   // uniform LDS.128
            acc[t].x += p.x*e0.x + p.y*e1.x + p.z*e2.x + p.w*e3.x;
            acc[t].y += p.x*e0.y + p.y*e1.y + p.z*e2.y + p.w*e3.y;
            acc[t].z += p.x*e0.z + p.y*e1.z + p.z*e2.z + p.w*e3.z;
            acc[t].w += p.x*e0.w + p.y*e1.w + p.z*e2.w + p.w*e3.w;
        }
    }
    __syncthreads();                 // all score reads done; buf reusable
    {   // write partials: [warp][t][h]
        float* dst = buf + (warp*8)*128;
        #pragma unroll
        for (int t = 0; t < 8; t++)
            *(float4*)(dst + t*128 + h0) = acc[t];
    }
    __syncthreads();
    float4 ctr;                      // this thread's final ct[t=warp][h0..h0+3]
    {
        int t = warp;
        float4 r = make_float4(0.f,0.f,0.f,0.f);
        #pragma unroll
        for (int sl = 0; sl < 8; sl++) {
            float4 v = *(const float4*)(buf + (sl*8 + t)*128 + h0);
            r.x += v.x; r.y += v.y; r.z += v.z; r.w += v.w;
        }
        float iv = invsum[t];
        ctr = make_float4(r.x*iv, r.y*iv, r.z*iv, r.w*iv);
    }
    __syncthreads();                 // partial reads done; buf reusable again

    // ---- build concat = [ct | q] in buf[0..2048), W chunks at buf[2048..) ----
    float* concat = buf;             // 8 t x 256 c
    float* Wsm    = buf + 2048;      // 128 o x 36 (32-c chunk, pad 36)
    *(float4*)(concat + warp*256 + h0) = ctr;
    {   // q half: 8 t x 32 float4 = 256 float4
        int t = tid >> 5, c4 = tid & 31;
        *(float4*)(concat + t*256 + 128 + c4*4) =
            *(const float4*)(q + (b*TT + t0 + t)*128 + c4*4);
    }
    int og = tid & 127;              // o
    int th = tid >> 7;               // t-half: t = th*4 + r
    float bval = __ldg(&bias[og]);
    float oacc[4] = {0.f, 0.f, 0.f, 0.f};

    #pragma unroll 1
    for (int hc = 0; hc < 8; hc++) {          // 32-c chunks of W
        __syncthreads();
        #pragma unroll
        for (int k = 0; k < 4; k++) {         // stage W chunk: 128 o x 32 c = 1024 float4
            int idx = tid + 256*k;
            int col = idx >> 3, kk = idx & 7;
            float4 w = *(const float4*)(Wout + col*256 + hc*32 + kk*4);
            *(float4*)(Wsm + col*36 + kk*4) = w;
        }
        __syncthreads();
        #pragma unroll
        for (int k8 = 0; k8 < 8; k8++) {
            float4 cv = *(const float4*)(Wsm + og*36 + k8*4);
            #pragma unroll
            for (int r = 0; r < 4; r++) {
                float4 rv = *(const float4*)(concat + (th*4 + r)*256 + hc*32 + k8*4);
                oacc[r] += rv.x*cv.x + rv.y*cv.y + rv.z*cv.z + rv.w*cv.w;
            }
        }
    }
    #pragma unroll
    for (int r = 0; r < 4; r++) {
        int t = t0 + th*4 + r;
        out[(b*TT + t)*128 + og] = tanhf(oacc[r] + bval);
    }
}

// ---------------------------------------------------------------------------
extern "C" void kernel_launch(void* const* d_in, const int* in_sizes, int n_in,
                              void* d_out, int out_size)
{
    (void)in_sizes; (void)n_in; (void)out_size;
    const float* q    = (const float*)d_in[0];
    const float* enc  = (const float*)d_in[1];
    const int*   lens = (const int*)  d_in[2];
    const float* Wh   = (const float*)d_in[3];
    const float* Ws   = (const float*)d_in[4];
    const float* v    = (const float*)d_in[5];
    const float* Wout = (const float*)d_in[6];
    const float* bias = (const float*)d_in[7];
    float* out = (float*)d_out;

    int sm1 = (32*128 + 128*36) * 4;            // 34816 B
    cudaFuncSetAttribute(k_proj, cudaFuncAttributeMaxDynamicSharedMemorySize, sm1);

    dim3 g1(128, 2);
    k_proj<<<g1, 256, sm1>>>(q, enc, Ws, Wh, v);
    k_scores<<<2048, 256>>>(lens);
    k_smct<<<512, 256>>>(enc, q, Wout, bias, out);
}

// round 16
// speedup vs baseline: 1.0784x; 1.0784x over previous
#include <cuda_runtime.h>
#include <cuda_fp16.h>
#include <cstdint>

#define BB 8
#define TT 512
#define SS 512
#define HH 128

// scratch (allocation-free rule: __device__ globals)
__device__ uint32_t g_WS2[BB*TT/2*HH];   // half2: (WS[t_even], WS[t_odd]) per h
__device__ uint32_t g_WH2[BB*SS*HH];     // half2: (WH, WH) duplicated
__device__ uint32_t g_V2 [HH];           // half2: (v, v) duplicated
__device__ float    g_SC [BB*TT*SS];     // raw masked scores (8 MB, L2-resident)
__device__ float    g_CT [BB*TT*HH];

__device__ __forceinline__ uint32_t tanh2_u(uint32_t a){
    uint32_t r; asm("tanh.approx.f16x2 %0, %1;" : "=r"(r) : "r"(a)); return r;
}
__device__ __forceinline__ void cp16(uint32_t smem_dst, const void* gsrc){
    asm volatile("cp.async.ca.shared.global [%0], [%1], 16;" :: "r"(smem_dst), "l"(gsrc));
}
#define CP_COMMIT() asm volatile("cp.async.commit_group;")
template<int N> __device__ __forceinline__ void cp_wait(){
    asm volatile("cp.async.wait_group %0;" :: "n"(N));
}

// ---------------------------------------------------------------------------
// K1: projections. grid (128, 2): y=0 -> WS(query,W_s) -> g_WS2 (t-paired h2),
//                                 y=1 -> WH(enc,W_h)   -> g_WH2 (dup h2).
// Block (0,0) also packs v into g_V2.
// ---------------------------------------------------------------------------
__global__ __launch_bounds__(256) void k_proj(
    const float* __restrict__ q, const float* __restrict__ enc,
    const float* __restrict__ Ws, const float* __restrict__ Wh,
    const float* __restrict__ vvec)
{
    extern __shared__ float sm[];
    float* insm = sm;            // 32 x 128
    float* Wsm  = sm + 32*128;   // 128 cols x 36

    const float* in; const float* W;
    if (blockIdx.y == 0) { in = q;   W = Ws; }
    else                 { in = enc; W = Wh; }
    int tid = threadIdx.x;
    int i0 = blockIdx.x * 32;

    if (blockIdx.x == 0 && blockIdx.y == 0 && tid < 128) {
        __half2 d = __half2half2(__float2half_rn(vvec[tid]));
        g_V2[tid] = *(uint32_t*)&d;
    }

    {
        const float4* inv = (const float4*)(in + i0*128);
        float4* insv = (float4*)insm;
        #pragma unroll
        for (int k = 0; k < 4; k++) insv[tid + 256*k] = inv[tid + 256*k];
    }

    int cg = tid & 31;
    int rg = tid >> 5;
    float acc[4][4];
    #pragma unroll
    for (int r = 0; r < 4; r++)
        #pragma unroll
        for (int j = 0; j < 4; j++) acc[r][j] = 0.f;

    #pragma unroll 1
    for (int hc = 0; hc < 4; hc++) {
        __syncthreads();
        #pragma unroll
        for (int k = 0; k < 4; k++) {
            int idx = tid + 256*k;
            int col = idx >> 3, kk = idx & 7;
            float4 w = *(const float4*)(W + col*128 + hc*32 + kk*4);
            *(float4*)(Wsm + col*36 + kk*4) = w;
        }
        __syncthreads();
        #pragma unroll
        for (int k8 = 0; k8 < 8; k8++) {
            float4 cv[4];
            #pragma unroll
            for (int j = 0; j < 4; j++)
                cv[j] = *(const float4*)(Wsm + (cg + 32*j)*36 + k8*4);
            float4 rv[4];
            #pragma unroll
            for (int r = 0; r < 4; r++)
                rv[r] = *(const float4*)(insm + (rg*4 + r)*128 + hc*32 + k8*4);
            #pragma unroll
            for (int r = 0; r < 4; r++)
                #pragma unroll
                for (int j = 0; j < 4; j++) {
                    acc[r][j] += rv[r].x*cv[j].x;
                    acc[r][j] += rv[r].y*cv[j].y;
                    acc[r][j] += rv[r].z*cv[j].z;
                    acc[r][j] += rv[r].w*cv[j].w;
                }
        }
    }
    if (blockIdx.y == 0) {
        #pragma unroll
        for (int r = 0; r < 4; r += 2)
            #pragma unroll
            for (int j = 0; j < 4; j++) {
                __half2 p = __floats2half2_rn(acc[r][j], acc[r+1][j]);  // x=even t
                int pair = (i0 + rg*4 + r) >> 1;
                g_WS2[pair*128 + cg + 32*j] = *(uint32_t*)&p;
            }
    } else {
        #pragma unroll
        for (int r = 0; r < 4; r++)
            #pragma unroll
            for (int j = 0; j < 4; j++) {
                __half2 d = __half2half2(__float2half_rn(acc[r][j]));
                g_WH2[(i0 + rg*4 + r)*128 + cg + 32*j] = *(uint32_t*)&d;
            }
    }
}

// ---------------------------------------------------------------------------
// K2: scores only. grid 2048 = (b, t-tile of 16, s-chunk of 64).
// Early-exit (write zeros) when whole s-chunk masked.
// ---------------------------------------------------------------------------
__global__ __launch_bounds__(256) void k_scores(
    const int* __restrict__ lens)
{
    __shared__ uint32_t s_wh[64*132];   // transposed s-chunk, pad 132
    __shared__ uint32_t s_ws[8*128];    // 8 t-pairs x 128 h
    __shared__ uint32_t s_v [128];      // dup half2 of v

    int bx = blockIdx.x;
    int b  = bx >> 8;
    int tt = (bx >> 3) & 31;
    int sc = bx & 7;
    int t0 = tt*16, s0 = sc*64;
    int tid = threadIdx.x;
    int len = __ldg(&lens[b]);

    if (s0 >= len) {   // fully masked: write zeros (reference quirk)
        int r = tid >> 4, c4 = tid & 15;
        *(float4*)(g_SC + (b*TT + t0 + r)*SS + s0 + c4*4) = make_float4(0.f,0.f,0.f,0.f);
        return;
    }

    uint32_t smbase = (uint32_t)__cvta_generic_to_shared(s_wh);
    {   // stage WH chunk (transposed, cp.async)
        const uint32_t* src = g_WH2 + (b*SS + s0)*128;
        #pragma unroll
        for (int k = 0; k < 8; k++) {
            int idx = tid + 256*k;            // 2048 x 16B
            int ss = idx >> 5, kk = idx & 31;
            cp16(smbase + (ss*132 + kk*4)*4, src + ss*128 + kk*4);
        }
        CP_COMMIT();
    }
    {   // stage ws pairs + v
        const uint32_t* wsrc = g_WS2 + (b*(TT/2) + t0/2)*128;
        #pragma unroll
        for (int k = 0; k < 4; k++) s_ws[tid + 256*k] = wsrc[tid + 256*k];
        if (tid < 128) s_v[tid] = g_V2[tid];
    }
    cp_wait<0>();
    __syncthreads();

    int warp = tid >> 5, lane = tid & 31;
    int tq = warp >> 1, sh = warp & 1;
    int s  = sh*32 + lane;
    const uint32_t* wsA = s_ws + (tq*2 + 0)*128;   // (t=4tq+0, 4tq+1)
    const uint32_t* wsB = s_ws + (tq*2 + 1)*128;   // (t=4tq+2, 4tq+3)
    const uint32_t* whrow = s_wh + s*132;

    float a0 = 0.f, a1 = 0.f, a2 = 0.f, a3 = 0.f;
    #pragma unroll
    for (int hb = 0; hb < 128; hb += 8) {      // flush f16 accumulators every 8 h
        __half2 accA = __float2half2_rn(0.f);
        __half2 accB = __float2half2_rn(0.f);
        #pragma unroll
        for (int g = 0; g < 8; g += 4) {
            uint4 wh4 = *(const uint4*)(whrow + hb + g);
            uint4 wA4 = *(const uint4*)(wsA + hb + g);
            uint4 wB4 = *(const uint4*)(wsB + hb + g);
            uint4 vv4 = *(const uint4*)(s_v + hb + g);
            #define STEP(WH, WA, WB, VV)                                     \
            {                                                                \
                __half2 hw = *(__half2*)&(WH);                               \
                __half2 aA = __hadd2(hw, *(__half2*)&(WA));                  \
                __half2 aB = __hadd2(hw, *(__half2*)&(WB));                  \
                uint32_t tA = tanh2_u(*(uint32_t*)&aA);                      \
                uint32_t tB = tanh2_u(*(uint32_t*)&aB);                      \
                __half2 v2 = *(__half2*)&(VV);                               \
                accA = __hfma2(v2, *(__half2*)&tA, accA);                    \
                accB = __hfma2(v2, *(__half2*)&tB, accB);                    \
            }
            STEP(wh4.x, wA4.x, wB4.x, vv4.x)
            STEP(wh4.y, wA4.y, wB4.y, vv4.y)
            STEP(wh4.z, wA4.z, wB4.z, vv4.z)
            STEP(wh4.w, wA4.w, wB4.w, vv4.w)
            #undef STEP
        }
        float2 fA = __half22float2(accA);
        float2 fB = __half22float2(accB);
        a0 += fA.x; a1 += fA.y;
        a2 += fB.x; a3 += fB.y;
    }
    int sg = s0 + s;
    float m = (sg < len) ? 1.f : 0.f;          // reference quirk: zero, not -inf
    g_SC[(b*TT + t0 + tq*4 + 0)*SS + sg] = a0 * m;
    g_SC[(b*TT + t0 + tq*4 + 1)*SS + sg] = a1 * m;
    g_SC[(b*TT + t0 + tq*4 + 2)*SS + sg] = a2 * m;
    g_SC[(b*TT + t0 + tq*4 + 3)*SS + sg] = a3 * m;
}

// ---------------------------------------------------------------------------
// K3: softmax + ct. grid 512 = (b, t-tile of 8), 256 threads, 4 CTAs/SM.
// ---------------------------------------------------------------------------
__global__ __launch_bounds__(256, 4) void k_smct(
    const float* __restrict__ enc)
{
    __shared__ float buf[8*8*128];   // 32KB; [0:4096) = scores (8x512) in ph1/2
    __shared__ float invsum[8];
    float* scores = buf;

    int tid = threadIdx.x;
    int b  = blockIdx.x >> 6;
    int t0 = (blockIdx.x & 63) * 8;
    int warp = tid >> 5, lane = tid & 31;

    {   // stage scores (cp.async, 16 KB, coalesced)
        uint32_t smbase = (uint32_t)__cvta_generic_to_shared(buf);
        const float* src = g_SC + (b*TT + t0)*SS;
        #pragma unroll
        for (int k = 0; k < 4; k++) {
            int idx = tid + 256*k;            // 1024 x 16B
            cp16(smbase + idx*16, src + idx*4);
        }
        CP_COMMIT();
        cp_wait<0>();
        __syncthreads();
    }

    // ---- softmax over full 512 (zeros included); 1 warp per row ----
    {
        int t = warp;
        float* row = scores + t*512;
        float loc[16];
        float mx = -1e30f;
        #pragma unroll
        for (int k = 0; k < 16; k++) { loc[k] = row[lane + 32*k]; mx = fmaxf(mx, loc[k]); }
        #pragma unroll
        for (int o = 16; o > 0; o >>= 1) mx = fmaxf(mx, __shfl_xor_sync(0xffffffffu, mx, o));
        float sum = 0.f;
        #pragma unroll
        for (int k = 0; k < 16; k++) {
            float p = __expf(loc[k] - mx);
            row[lane + 32*k] = p;
            sum += p;
        }
        #pragma unroll
        for (int o = 16; o > 0; o >>= 1) sum += __shfl_xor_sync(0xffffffffu, sum, o);
        if (lane == 0) invsum[t] = 1.f / sum;
    }
    __syncthreads();

    // ---- ct partials: warp w covers s in [w*64, w*64+64), all 8 t ----
    int h0 = lane * 4;
    int sbase = warp * 64;
    float4 acc[8];
    #pragma unroll
    for (int t = 0; t < 8; t++) acc[t] = make_float4(0.f,0.f,0.f,0.f);

    const float* eb = enc + (b*SS)*128;
    #pragma unroll 2
    for (int s4 = 0; s4 < 16; s4++) {
        float4 e0 = __ldg((const float4*)(eb + (sbase + s4*4 + 0)*128 + h0));
        float4 e1 = __ldg((const float4*)(eb + (sbase + s4*4 + 1)*128 + h0));
        float4 e2 = __ldg((const float4*)(eb + (sbase + s4*4 + 2)*128 + h0));
        float4 e3 = __ldg((const float4*)(eb + (sbase + s4*4 + 3)*128 + h0));
        const float* ps = scores + sbase + s4*4;
        #pragma unroll
        for (int t = 0; t < 8; t++) {
            float4 p = *(const float4*)(ps + t*512);   // uniform LDS.128
            acc[t].x += p.x*e0.x + p.y*e1.x + p.z*e2.x + p.w*e3.x;
            acc[t].y += p.x*e0.y + p.y*e1.y + p.z*e2.y + p.w*e3.y;
            acc[t].z += p.x*e0.z + p.y*e1.z + p.z*e2.z + p.w*e3.z;
            acc[t].w += p.x*e0.w + p.y*e1.w + p.z*e2.w + p.w*e3.w;
        }
    }
    __syncthreads();                 // all score reads done; buf reusable
    {   // write partials: [warp][t][h]
        float* dst = buf + (warp*8)*128;
        #pragma unroll
        for (int t = 0; t < 8; t++)
            *(float4*)(dst + t*128 + h0) = acc[t];
    }
    __syncthreads();
    {   // reduce 8 slices; thread = (t = warp, h-quad = lane)
        int t = warp;
        float4 r = make_float4(0.f,0.f,0.f,0.f);
        #pragma unroll
        for (int sl = 0; sl < 8; sl++) {
            float4 v = *(const float4*)(buf + (sl*8 + t)*128 + h0);
            r.x += v.x; r.y += v.y; r.z += v.z; r.w += v.w;
        }
        float iv = invsum[t];
        r.x *= iv; r.y *= iv; r.z *= iv; r.w *= iv;
        *(float4*)(g_CT + (b*TT + t0 + t)*128 + h0) = r;
    }
}

// ---------------------------------------------------------------------------
// K4: out = tanh(W_out . concat + b), o-HALF split of the R12 structure.
// grid 256 = (b, t-tile of 32, o-half of 64); 256 threads; thread = 4t x 2o.
// W half staged in 8 chunks of 32 c into 64x36 pad layout. All SMs busy.
// ---------------------------------------------------------------------------
__global__ __launch_bounds__(256) void k_out(
    const float* __restrict__ q, const float* __restrict__ Wout,
    const float* __restrict__ bias, float* __restrict__ out)
{
    extern __shared__ float sm[];
    float* concat = sm;              // 32 x 256 (32 KB)
    float* Wsm    = sm + 32*256;     // 64 o x 36 (32-c chunk, pad 36; 9 KB)
    float* bsm    = Wsm + 64*36;     // 64

    int tid = threadIdx.x;
    int bx  = blockIdx.x;
    int b   = bx >> 5;               // 8 b
    int tt  = (bx >> 1) & 15;        // 16 t-tiles of 32
    int oh  = bx & 1;                // 2 o-halves
    int t0  = tt*32, o0 = oh*64;

    {   // stage concat: 32 t x 256 c = 2048 float4
        #pragma unroll
        for (int k = 0; k < 8; k++) {
            int idx = tid + 256*k;
            int t = idx >> 6, c4 = idx & 63;
            float4 v;
            if (c4 < 32) v = *(const float4*)(g_CT + (b*TT + t0 + t)*128 + c4*4);
            else         v = *(const float4*)(q    + (b*TT + t0 + t)*128 + (c4-32)*4);
            *(float4*)(concat + t*256 + c4*4) = v;
        }
    }
    if (tid < 64) bsm[tid] = bias[o0 + tid];

    int cg = tid & 31;          // o = o0 + cg + 32*j, j<2
    int rg = tid >> 5;          // t rows = rg*4 + r (8 groups x 4 = 32 t)
    float acc[4][2];
    #pragma unroll
    for (int r = 0; r < 4; r++) { acc[r][0] = 0.f; acc[r][1] = 0.f; }

    #pragma unroll 1
    for (int hc = 0; hc < 8; hc++) {          // 32-c chunks of W half
        __syncthreads();
        #pragma unroll
        for (int k = 0; k < 2; k++) {         // stage: 64 o x 32 c = 512 float4
            int idx = tid + 256*k;
            int col = idx >> 3, kk = idx & 7;
            float4 w = *(const float4*)(Wout + (o0 + col)*256 + hc*32 + kk*4);
            *(float4*)(Wsm + col*36 + kk*4) = w;
        }
        __syncthreads();
        #pragma unroll
        for (int k8 = 0; k8 < 8; k8++) {
            float4 cv[2];
            #pragma unroll
            for (int j = 0; j < 2; j++)
                cv[j] = *(const float4*)(Wsm + (cg + 32*j)*36 + k8*4);
            float4 rv[4];
            #pragma unroll
            for (int r = 0; r < 4; r++)
                rv[r] = *(const float4*)(concat + (rg*4 + r)*256 + hc*32 + k8*4);
            #pragma unroll
            for (int r = 0; r < 4; r++)
                #pragma unroll
                for (int j = 0; j < 2; j++) {
                    acc[r][j] += rv[r].x*cv[j].x;
                    acc[r][j] += rv[r].y*cv[j].y;
                    acc[r][j] += rv[r].z*cv[j].z;
                    acc[r][j] += rv[r].w*cv[j].w;
                }
        }
    }
    #pragma unroll
    for (int r = 0; r < 4; r++) {
        int t = t0 + rg*4 + r;
        #pragma unroll
        for (int j = 0; j < 2; j++)
            out[(b*TT + t)*128 + o0 + cg + 32*j] = tanhf(acc[r][j] + bsm[cg + 32*j]);
    }
}

// ---------------------------------------------------------------------------
extern "C" void kernel_launch(void* const* d_in, const int* in_sizes, int n_in,
                              void* d_out, int out_size)
{
    (void)in_sizes; (void)n_in; (void)out_size;
    const float* q    = (const float*)d_in[0];
    const float* enc  = (const float*)d_in[1];
    const int*   lens = (const int*)  d_in[2];
    const float* Wh   = (const float*)d_in[3];
    const float* Ws   = (const float*)d_in[4];
    const float* v    = (const float*)d_in[5];
    const float* Wout = (const float*)d_in[6];
    const float* bias = (const float*)d_in[7];
    float* out = (float*)d_out;

    int sm1 = (32*128 + 128*36) * 4;            // 34816 B
    int sm4 = (32*256 + 64*36 + 64) * 4;        // 42240 B
    cudaFuncSetAttribute(k_proj, cudaFuncAttributeMaxDynamicSharedMemorySize, sm1);
    cudaFuncSetAttribute(k_out,  cudaFuncAttributeMaxDynamicSharedMemorySize, sm4);

    dim3 g1(128, 2);
    k_proj<<<g1, 256, sm1>>>(q, enc, Ws, Wh, v);
    k_scores<<<2048, 256>>>(lens);
    k_smct<<<512, 256>>>(enc);
    k_out<<<256, 256, sm4>>>(q, Wout, bias, out);
}

// round 17
// speedup vs baseline: 1.1300x; 1.0479x over previous
#include <cuda_runtime.h>
#include <cuda_fp16.h>
#include <cstdint>

#define BB 8
#define TT 512
#define SS 512
#define HH 128

// scratch (allocation-free rule: __device__ globals)
__device__ uint32_t g_WS2[BB*TT/2*HH];   // half2: (WS[t_even], WS[t_odd]) per h
__device__ uint32_t g_WH2[BB*SS*HH];     // half2: (WH, WH) duplicated
__device__ uint32_t g_V2 [HH];           // half2: (v, v) duplicated
__device__ float    g_SC [BB*TT*SS];     // raw masked scores (8 MB, L2-resident)
__device__ float    g_CT [BB*TT*HH];

__device__ __forceinline__ uint32_t tanh2_u(uint32_t a){
    uint32_t r; asm("tanh.approx.f16x2 %0, %1;" : "=r"(r) : "r"(a)); return r;
}
__device__ __forceinline__ void cp16(uint32_t smem_dst, const void* gsrc){
    asm volatile("cp.async.ca.shared.global [%0], [%1], 16;" :: "r"(smem_dst), "l"(gsrc));
}
#define CP_COMMIT() asm volatile("cp.async.commit_group;")
template<int N> __device__ __forceinline__ void cp_wait(){
    asm volatile("cp.async.wait_group %0;" :: "n"(N));
}
#define H2(u) (*(__half2*)&(u))

// ---------------------------------------------------------------------------
// K1: projections in fp16. grid (128, 2): y=0 -> WS(q,Ws) -> g_WS2 (t-paired),
//                                         y=1 -> WH(enc,Wh) -> g_WH2 (dup).
// Whole W staged once as half2 (128 x 68 pad, LDS.128 conflict-free: start
// bank 4l mod 32). Thread = 4r x 4c; per 4 h2: 8 LDS.128 + 64 HFMA2.
// Two half2 accumulators per output (h-halves), one f32 flush at the end.
// Block (0,0) also packs v into g_V2.
// ---------------------------------------------------------------------------
__global__ __launch_bounds__(256) void k_proj(
    const float* __restrict__ q, const float* __restrict__ enc,
    const float* __restrict__ Ws, const float* __restrict__ Wh,
    const float* __restrict__ vvec)
{
    extern __shared__ uint32_t smu[];
    uint32_t* in2 = smu;            // 32 rows x 64 h2
    uint32_t* W2  = smu + 32*64;    // 128 cols x 68 (pad)

    const float* in; const float* W;
    if (blockIdx.y == 0) { in = q;   W = Ws; }
    else                 { in = enc; W = Wh; }
    int tid = threadIdx.x;
    int i0 = blockIdx.x * 32;

    if (blockIdx.x == 0 && blockIdx.y == 0 && tid < 128) {
        __half2 d = __half2half2(__float2half_rn(vvec[tid]));
        g_V2[tid] = *(uint32_t*)&d;
    }

    {   // stage input rows: 32 x 128 f32 -> half2 (1024 float4)
        #pragma unroll
        for (int k = 0; k < 4; k++) {
            int idx = tid + 256*k;
            int r = idx >> 5, h4 = idx & 31;
            float4 x = *(const float4*)(in + (i0 + r)*128 + h4*4);
            __half2 lo = __floats2half2_rn(x.x, x.y);
            __half2 hi = __floats2half2_rn(x.z, x.w);
            uint2 p = make_uint2(*(uint32_t*)&lo, *(uint32_t*)&hi);
            *(uint2*)(in2 + r*64 + h4*2) = p;
        }
    }
    {   // stage W: 128 x 128 f32 -> half2 (4096 float4)
        #pragma unroll 4
        for (int k = 0; k < 16; k++) {
            int idx = tid + 256*k;
            int col = idx >> 5, h4 = idx & 31;
            float4 x = *(const float4*)(W + col*128 + h4*4);
            __half2 lo = __floats2half2_rn(x.x, x.y);
            __half2 hi = __floats2half2_rn(x.z, x.w);
            uint2 p = make_uint2(*(uint32_t*)&lo, *(uint32_t*)&hi);
            *(uint2*)(W2 + col*68 + h4*2) = p;
        }
    }
    __syncthreads();

    int cg = tid & 31;          // cols = cg + 32*j
    int rg = tid >> 5;          // rows = rg*4 + r (warp-uniform)
    __half2 accL[4][4], accH[4][4];
    __half2 z2 = __float2half2_rn(0.f);
    #pragma unroll
    for (int r = 0; r < 4; r++)
        #pragma unroll
        for (int j = 0; j < 4; j++) { accL[r][j] = z2; accH[r][j] = z2; }

    #pragma unroll
    for (int hf = 0; hf < 2; hf++) {          // h2 halves: [0,32) and [32,64)
        #pragma unroll
        for (int g = 0; g < 8; g++) {         // 4 h2 per group
            int hb = hf*32 + g*4;
            uint4 cv[4];
            #pragma unroll
            for (int j = 0; j < 4; j++)
                cv[j] = *(const uint4*)(W2 + (cg + 32*j)*68 + hb);
            uint4 rv[4];
            #pragma unroll
            for (int r = 0; r < 4; r++)
                rv[r] = *(const uint4*)(in2 + (rg*4 + r)*64 + hb);
            #pragma unroll
            for (int r = 0; r < 4; r++)
                #pragma unroll
                for (int j = 0; j < 4; j++) {
                    __half2 a = (hf == 0) ? accL[r][j] : accH[r][j];
                    a = __hfma2(H2(rv[r].x), H2(cv[j].x), a);
                    a = __hfma2(H2(rv[r].y), H2(cv[j].y), a);
                    a = __hfma2(H2(rv[r].z), H2(cv[j].z), a);
                    a = __hfma2(H2(rv[r].w), H2(cv[j].w), a);
                    if (hf == 0) accL[r][j] = a; else accH[r][j] = a;
                }
        }
    }
    float acc[4][4];
    #pragma unroll
    for (int r = 0; r < 4; r++)
        #pragma unroll
        for (int j = 0; j < 4; j++) {
            float2 l = __half22float2(accL[r][j]);
            float2 h = __half22float2(accH[r][j]);
            acc[r][j] = (l.x + l.y) + (h.x + h.y);
        }

    if (blockIdx.y == 0) {
        #pragma unroll
        for (int r = 0; r < 4; r += 2)
            #pragma unroll
            for (int j = 0; j < 4; j++) {
                __half2 p = __floats2half2_rn(acc[r][j], acc[r+1][j]);  // x=even t
                int pair = (i0 + rg*4 + r) >> 1;
                g_WS2[pair*128 + cg + 32*j] = *(uint32_t*)&p;
            }
    } else {
        #pragma unroll
        for (int r = 0; r < 4; r++)
            #pragma unroll
            for (int j = 0; j < 4; j++) {
                __half2 d = __half2half2(__float2half_rn(acc[r][j]));
                g_WH2[(i0 + rg*4 + r)*128 + cg + 32*j] = *(uint32_t*)&d;
            }
    }
}

// ---------------------------------------------------------------------------
// K2: scores only. grid 2048 = (b, t-tile of 16, s-chunk of 64).
// Early-exit (write zeros) when whole s-chunk masked.
// ---------------------------------------------------------------------------
__global__ __launch_bounds__(256) void k_scores(
    const int* __restrict__ lens)
{
    __shared__ uint32_t s_wh[64*132];   // transposed s-chunk, pad 132
    __shared__ uint32_t s_ws[8*128];    // 8 t-pairs x 128 h
    __shared__ uint32_t s_v [128];      // dup half2 of v

    int bx = blockIdx.x;
    int b  = bx >> 8;
    int tt = (bx >> 3) & 31;
    int sc = bx & 7;
    int t0 = tt*16, s0 = sc*64;
    int tid = threadIdx.x;
    int len = __ldg(&lens[b]);

    if (s0 >= len) {   // fully masked: write zeros (reference quirk)
        int r = tid >> 4, c4 = tid & 15;
        *(float4*)(g_SC + (b*TT + t0 + r)*SS + s0 + c4*4) = make_float4(0.f,0.f,0.f,0.f);
        return;
    }

    uint32_t smbase = (uint32_t)__cvta_generic_to_shared(s_wh);
    {   // stage WH chunk (transposed, cp.async)
        const uint32_t* src = g_WH2 + (b*SS + s0)*128;
        #pragma unroll
        for (int k = 0; k < 8; k++) {
            int idx = tid + 256*k;            // 2048 x 16B
            int ss = idx >> 5, kk = idx & 31;
            cp16(smbase + (ss*132 + kk*4)*4, src + ss*128 + kk*4);
        }
        CP_COMMIT();
    }
    {   // stage ws pairs + v
        const uint32_t* wsrc = g_WS2 + (b*(TT/2) + t0/2)*128;
        #pragma unroll
        for (int k = 0; k < 4; k++) s_ws[tid + 256*k] = wsrc[tid + 256*k];
        if (tid < 128) s_v[tid] = g_V2[tid];
    }
    cp_wait<0>();
    __syncthreads();

    int warp = tid >> 5, lane = tid & 31;
    int tq = warp >> 1, sh = warp & 1;
    int s  = sh*32 + lane;
    const uint32_t* wsA = s_ws + (tq*2 + 0)*128;   // (t=4tq+0, 4tq+1)
    const uint32_t* wsB = s_ws + (tq*2 + 1)*128;   // (t=4tq+2, 4tq+3)
    const uint32_t* whrow = s_wh + s*132;

    float a0 = 0.f, a1 = 0.f, a2 = 0.f, a3 = 0.f;
    #pragma unroll
    for (int hb = 0; hb < 128; hb += 8) {      // flush f16 accumulators every 8 h
        __half2 accA = __float2half2_rn(0.f);
        __half2 accB = __float2half2_rn(0.f);
        #pragma unroll
        for (int g = 0; g < 8; g += 4) {
            uint4 wh4 = *(const uint4*)(whrow + hb + g);
            uint4 wA4 = *(const uint4*)(wsA + hb + g);
            uint4 wB4 = *(const uint4*)(wsB + hb + g);
            uint4 vv4 = *(const uint4*)(s_v + hb + g);
            #define STEP(WH, WA, WB, VV)                                     \
            {                                                                \
                __half2 hw = *(__half2*)&(WH);                               \
                __half2 aA = __hadd2(hw, *(__half2*)&(WA));                  \
                __half2 aB = __hadd2(hw, *(__half2*)&(WB));                  \
                uint32_t tA = tanh2_u(*(uint32_t*)&aA);                      \
                uint32_t tB = tanh2_u(*(uint32_t*)&aB);                      \
                __half2 v2 = *(__half2*)&(VV);                               \
                accA = __hfma2(v2, *(__half2*)&tA, accA);                    \
                accB = __hfma2(v2, *(__half2*)&tB, accB);                    \
            }
            STEP(wh4.x, wA4.x, wB4.x, vv4.x)
            STEP(wh4.y, wA4.y, wB4.y, vv4.y)
            STEP(wh4.z, wA4.z, wB4.z, vv4.z)
            STEP(wh4.w, wA4.w, wB4.w, vv4.w)
            #undef STEP
        }
        float2 fA = __half22float2(accA);
        float2 fB = __half22float2(accB);
        a0 += fA.x; a1 += fA.y;
        a2 += fB.x; a3 += fB.y;
    }
    int sg = s0 + s;
    float m = (sg < len) ? 1.f : 0.f;          // reference quirk: zero, not -inf
    g_SC[(b*TT + t0 + tq*4 + 0)*SS + sg] = a0 * m;
    g_SC[(b*TT + t0 + tq*4 + 1)*SS + sg] = a1 * m;
    g_SC[(b*TT + t0 + tq*4 + 2)*SS + sg] = a2 * m;
    g_SC[(b*TT + t0 + tq*4 + 3)*SS + sg] = a3 * m;
}

// ---------------------------------------------------------------------------
// K3: softmax + ct. grid 512 = (b, t-tile of 8), 256 threads, 4 CTAs/SM.
// ---------------------------------------------------------------------------
__global__ __launch_bounds__(256, 4) void k_smct(
    const float* __restrict__ enc)
{
    __shared__ float buf[8*8*128];   // 32KB; [0:4096) = scores (8x512) in ph1/2
    __shared__ float invsum[8];
    float* scores = buf;

    int tid = threadIdx.x;
    int b  = blockIdx.x >> 6;
    int t0 = (blockIdx.x & 63) * 8;
    int warp = tid >> 5, lane = tid & 31;

    {   // stage scores (cp.async, 16 KB, coalesced)
        uint32_t smbase = (uint32_t)__cvta_generic_to_shared(buf);
        const float* src = g_SC + (b*TT + t0)*SS;
        #pragma unroll
        for (int k = 0; k < 4; k++) {
            int idx = tid + 256*k;            // 1024 x 16B
            cp16(smbase + idx*16, src + idx*4);
        }
        CP_COMMIT();
        cp_wait<0>();
        __syncthreads();
    }

    // ---- softmax over full 512 (zeros included); 1 warp per row ----
    {
        int t = warp;
        float* row = scores + t*512;
        float loc[16];
        float mx = -1e30f;
        #pragma unroll
        for (int k = 0; k < 16; k++) { loc[k] = row[lane + 32*k]; mx = fmaxf(mx, loc[k]); }
        #pragma unroll
        for (int o = 16; o > 0; o >>= 1) mx = fmaxf(mx, __shfl_xor_sync(0xffffffffu, mx, o));
        float sum = 0.f;
        #pragma unroll
        for (int k = 0; k < 16; k++) {
            float p = __expf(loc[k] - mx);
            row[lane + 32*k] = p;
            sum += p;
        }
        #pragma unroll
        for (int o = 16; o > 0; o >>= 1) sum += __shfl_xor_sync(0xffffffffu, sum, o);
        if (lane == 0) invsum[t] = 1.f / sum;
    }
    __syncthreads();

    // ---- ct partials: warp w covers s in [w*64, w*64+64), all 8 t ----
    int h0 = lane * 4;
    int sbase = warp * 64;
    float4 acc[8];
    #pragma unroll
    for (int t = 0; t < 8; t++) acc[t] = make_float4(0.f,0.f,0.f,0.f);

    const float* eb = enc + (b*SS)*128;
    #pragma unroll 2
    for (int s4 = 0; s4 < 16; s4++) {
        float4 e0 = __ldg((const float4*)(eb + (sbase + s4*4 + 0)*128 + h0));
        float4 e1 = __ldg((const float4*)(eb + (sbase + s4*4 + 1)*128 + h0));
        float4 e2 = __ldg((const float4*)(eb + (sbase + s4*4 + 2)*128 + h0));
        float4 e3 = __ldg((const float4*)(eb + (sbase + s4*4 + 3)*128 + h0));
        const float* ps = scores + sbase + s4*4;
        #pragma unroll
        for (int t = 0; t < 8; t++) {
            float4 p = *(const float4*)(ps + t*512);   // uniform LDS.128
            acc[t].x += p.x*e0.x + p.y*e1.x + p.z*e2.x + p.w*e3.x;
            acc[t].y += p.x*e0.y + p.y*e1.y + p.z*e2.y + p.w*e3.y;
            acc[t].z += p.x*e0.z + p.y*e1.z + p.z*e2.z + p.w*e3.z;
            acc[t].w += p.x*e0.w + p.y*e1.w + p.z*e2.w + p.w*e3.w;
        }
    }
    __syncthreads();                 // all score reads done; buf reusable
    {   // write partials: [warp][t][h]
        float* dst = buf + (warp*8)*128;
        #pragma unroll
        for (int t = 0; t < 8; t++)
            *(float4*)(dst + t*128 + h0) = acc[t];
    }
    __syncthreads();
    {   // reduce 8 slices; thread = (t = warp, h-quad = lane)
        int t = warp;
        float4 r = make_float4(0.f,0.f,0.f,0.f);
        #pragma unroll
        for (int sl = 0; sl < 8; sl++) {
            float4 v = *(const float4*)(buf + (sl*8 + t)*128 + h0);
            r.x += v.x; r.y += v.y; r.z += v.z; r.w += v.w;
        }
        float iv = invsum[t];
        r.x *= iv; r.y *= iv; r.z *= iv; r.w *= iv;
        *(float4*)(g_CT + (b*TT + t0 + t)*128 + h0) = r;
    }
}

// ---------------------------------------------------------------------------
// K4: out = tanh(W_out . concat + b) — R12 structure (best total).
// grid 128 = (b, t-tile of 32); 256 threads; thread = 4t x 4o (o strided 32);
// W staged in 8 chunks of 32 c into 128x36 pad layout.
// ---------------------------------------------------------------------------
__global__ __launch_bounds__(256) void k_out(
    const float* __restrict__ q, const float* __restrict__ Wout,
    const float* __restrict__ bias, float* __restrict__ out)
{
    extern __shared__ float sm[];
    float* concat = sm;              // 32 x 256
    float* Wsm    = sm + 32*256;     // 128 o x 36 (32-c chunk, pad 36)
    float* bsm    = Wsm + 128*36;    // 128

    int tid = threadIdx.x;
    int b  = blockIdx.x >> 4;
    int t0 = (blockIdx.x & 15) * 32;

    {   // stage concat: 32 t x 256 c = 2048 float4
        #pragma unroll
        for (int k = 0; k < 8; k++) {
            int idx = tid + 256*k;
            int t = idx >> 6, c4 = idx & 63;
            float4 v;
            if (c4 < 32) v = *(const float4*)(g_CT + (b*TT + t0 + t)*128 + c4*4);
            else         v = *(const float4*)(q    + (b*TT + t0 + t)*128 + (c4-32)*4);
            *(float4*)(concat + t*256 + c4*4) = v;
        }
    }
    if (tid < 128) bsm[tid] = bias[tid];

    int cg = tid & 31;          // o = cg + 32*j
    int rg = tid >> 5;          // t rows = rg*4 + r
    float acc[4][4];
    #pragma unroll
    for (int r = 0; r < 4; r++)
        #pragma unroll
        for (int j = 0; j < 4; j++) acc[r][j] = 0.f;

    #pragma unroll 1
    for (int hc = 0; hc < 8; hc++) {          // 32-c chunks of W
        __syncthreads();
        #pragma unroll
        for (int k = 0; k < 4; k++) {         // stage W chunk: 128 o x 32 c = 1024 float4
            int idx = tid + 256*k;
            int col = idx >> 3, kk = idx & 7;
            float4 w = *(const float4*)(Wout + col*256 + hc*32 + kk*4);
            *(float4*)(Wsm + col*36 + kk*4) = w;
        }
        __syncthreads();
        #pragma unroll
        for (int k8 = 0; k8 < 8; k8++) {
            float4 cv[4];
            #pragma unroll
            for (int j = 0; j < 4; j++)
                cv[j] = *(const float4*)(Wsm + (cg + 32*j)*36 + k8*4);
            float4 rv[4];
            #pragma unroll
            for (int r = 0; r < 4; r++)
                rv[r] = *(const float4*)(concat + (rg*4 + r)*256 + hc*32 + k8*4);
            #pragma unroll
            for (int r = 0; r < 4; r++)
                #pragma unroll
                for (int j = 0; j < 4; j++) {
                    acc[r][j] += rv[r].x*cv[j].x;
                    acc[r][j] += rv[r].y*cv[j].y;
                    acc[r][j] += rv[r].z*cv[j].z;
                    acc[r][j] += rv[r].w*cv[j].w;
                }
        }
    }
    #pragma unroll
    for (int r = 0; r < 4; r++) {
        int t = t0 + rg*4 + r;
        #pragma unroll
        for (int j = 0; j < 4; j++)
            out[(b*TT + t)*128 + cg + 32*j] = tanhf(acc[r][j] + bsm[cg + 32*j]);
    }
}

// ---------------------------------------------------------------------------
extern "C" void kernel_launch(void* const* d_in, const int* in_sizes, int n_in,
                              void* d_out, int out_size)
{
    (void)in_sizes; (void)n_in; (void)out_size;
    const float* q    = (const float*)d_in[0];
    const float* enc  = (const float*)d_in[1];
    const int*   lens = (const int*)  d_in[2];
    const float* Wh   = (const float*)d_in[3];
    const float* Ws   = (const float*)d_in[4];
    const float* v    = (const float*)d_in[5];
    const float* Wout = (const float*)d_in[6];
    const float* bias = (const float*)d_in[7];
    float* out = (float*)d_out;

    int sm1 = (32*64 + 128*68) * 4;             // 43008 B (half2 layout)
    int sm4 = (32*256 + 128*36 + 128) * 4;      // 51712 B
    cudaFuncSetAttribute(k_proj, cudaFuncAttributeMaxDynamicSharedMemorySize, sm1);
    cudaFuncSetAttribute(k_out,  cudaFuncAttributeMaxDynamicSharedMemorySize, sm4);

    dim3 g1(128, 2);
    k_proj<<<g1, 256, sm1>>>(q, enc, Ws, Wh, v);
    k_scores<<<2048, 256>>>(lens);
    k_smct<<<512, 256>>>(enc);
    k_out<<<128, 256, sm4>>>(q, Wout, bias, out);
}